// round 1
// baseline (speedup 1.0000x reference)
#include <cuda_runtime.h>
#include <math.h>

// Problem constants
#define NBATCH 16
#define NC1 8
#define NC2 16
#define NM 63      /* k1 = m-31, m in [0,63) */
#define NK2 32     /* k2 in [0,32) */
#define NF (NM*NK2)  /* 2016 frequency points */
#define NPIX 16384   /* 128*128 */

// ---------------- device scratch (no allocations allowed) ----------------
__device__ float   g_ksym[128*4096];        // symmetrized kernel [8*16][64][64]
__device__ float2  g_Kf[128*NF];            // K spectrum   [i*16+j][m][k2]
__device__ float2  g_Ff[128*NF];            // F spectrum   [b*8+i][m][k2]
__device__ float2  g_Cf[256*NF];            // conv spectrum [b*16+j][m][k2]
__device__ float   g_u[256*NPIX];           // u fields [b*16+j][128][128]
__device__ float   g_v[256*NPIX];
// twiddle tables
__device__ float2  g_Ey[64*32];             // e^{-2pi i k2 y/64}   [y][k2]
__device__ float2  g_Ex[64*64];             // e^{-2pi i (m-31) x/64} [m][x] (m=63 row unused)
__device__ float2  g_WxT[63*128];           // e^{+2pi i (m-31) n1/128} [m][n1]
__device__ float2  g_WyT[32*128];           // scaled e^{+2pi i k2 n2/128} [k2][n2]
__device__ float   g_MU[NF];                // imag multiplier for u:  ky/den
__device__ float   g_MV[NF];                // imag multiplier for v: -kx/den

// ---------------- table init (cheap, runs every launch; deterministic) ----
__global__ void k_init() {
    int t = threadIdx.x;
    for (int idx = t; idx < 64*32; idx += 256) {
        int y = idx >> 5, k2 = idx & 31;
        float s, c; sincospif(-2.0f * (float)(k2*y) / 64.0f, &s, &c);
        g_Ey[idx] = make_float2(c, s);
    }
    for (int idx = t; idx < 64*64; idx += 256) {
        int m = idx >> 6, x = idx & 63; int k1 = m - 31;
        float s, c; sincospif(-2.0f * (float)(k1*x) / 64.0f, &s, &c);
        g_Ex[idx] = make_float2(c, s);
    }
    for (int idx = t; idx < 63*128; idx += 256) {
        int m = idx >> 7, n1 = idx & 127; int k1 = m - 31;
        float s, c; sincospif(2.0f * (float)(k1*n1) / 128.0f, &s, &c);
        g_WxT[idx] = make_float2(c, s);
    }
    for (int idx = t; idx < 32*128; idx += 256) {
        int k2 = idx >> 7, n2 = idx & 127;
        float s, c; sincospif(2.0f * (float)(k2*n2) / 128.0f, &s, &c);
        float sc = ((k2 == 0) ? 1.0f : 2.0f) * (2.0f / 16384.0f); // hermitian double * upsample*2 / 128^2
        g_WyT[idx] = make_float2(c * sc, s * sc);
    }
    for (int idx = t; idx < NF; idx += 256) {
        int m = idx >> 5, k2 = idx & 31; int k1 = m - 31;
        float den = (float)(k1*k1 + k2*k2);
        if (den == 0.0f) den = 1.0f;
        g_MU[idx] =  (float)k2 / den;
        g_MV[idx] = -(float)k1 / den;
    }
}

// ---------------- D4 kernel symmetrization ----------------
__global__ void k_sym(const float* __restrict__ kin) {
    int idx = blockIdx.x * 256 + threadIdx.x;     // 128*4096 total
    int ch = idx >> 12;
    int rem = idx & 4095;
    int a = rem >> 6, b = rem & 63;
    int na = (64 - a) & 63, nb = (64 - b) & 63;
    const float* s = kin + ch * 4096;
    float v = s[a*64 + b]   + s[nb*64 + a]  + s[na*64 + nb] + s[b*64 + na]
            + s[b*64 + a]   + s[a*64 + nb]  + s[nb*64 + na] + s[na*64 + b];
    g_ksym[idx] = v * 0.125f;
}

// ---------------- forward DFT to the 63x32 grid ----------------
// One block per channel. ch<128: symmetrized kernel -> g_Kf ; ch>=128: f -> g_Ff
__global__ void __launch_bounds__(256) k_fft64(const float* __restrict__ f) {
    __shared__ float  ss[4096];      // [x][y]
    __shared__ float2 sA[2048];      // [x][k2]
    int ch = blockIdx.x;
    const float* src = (ch < 128) ? (g_ksym + ch*4096) : (f + (ch-128)*4096);
    int t = threadIdx.x;
    for (int i = t; i < 4096; i += 256) ss[i] = src[i];
    __syncthreads();
    int k2 = t & 31, grp = t >> 5;
    // stage A: A[x][k2] = sum_y s[x][y] * Ey[y][k2]
    {
        float2 acc[8];
        #pragma unroll
        for (int r = 0; r < 8; r++) acc[r] = make_float2(0.f, 0.f);
        for (int y = 0; y < 64; y++) {
            float2 e = g_Ey[y*32 + k2];
            #pragma unroll
            for (int r = 0; r < 8; r++) {
                float sv = ss[(grp*8 + r)*64 + y];
                acc[r].x = fmaf(sv, e.x, acc[r].x);
                acc[r].y = fmaf(sv, e.y, acc[r].y);
            }
        }
        #pragma unroll
        for (int r = 0; r < 8; r++) sA[(grp*8 + r)*32 + k2] = acc[r];
    }
    __syncthreads();
    // stage B: F[m][k2] = sum_x Ex[m][x] * A[x][k2]
    {
        float2 acc[8];
        #pragma unroll
        for (int r = 0; r < 8; r++) acc[r] = make_float2(0.f, 0.f);
        for (int x = 0; x < 64; x++) {
            #pragma unroll
            for (int r = 0; r < 8; r++) {
                int m = grp*8 + r;            // 0..63 (m=63 uses padded Ex row, discarded)
                float2 e = g_Ex[m*64 + x];
                float2 a = sA[x*32 + k2];
                acc[r].x = fmaf(e.x, a.x, fmaf(-e.y, a.y, acc[r].x));
                acc[r].y = fmaf(e.x, a.y, fmaf( e.y, a.x, acc[r].y));
            }
        }
        float2* dstF = (ch < 128) ? (g_Kf + ch*NF) : (g_Ff + (ch-128)*NF);
        #pragma unroll
        for (int r = 0; r < 8; r++) {
            int m = grp*8 + r;
            if (m < 63) dstF[m*32 + k2] = acc[r];
        }
    }
}

// ---------------- channel contraction: C[b,j] = sum_i F[b,i] * K[i,j] ----------------
__global__ void k_conv() {
    int idx = blockIdx.x * 256 + threadIdx.x;   // (b*16+j)*NF + mk, 516096 total
    int mk = idx % NF;
    int bj = idx / NF;
    int b = bj >> 4, j = bj & 15;
    float2 acc = make_float2(0.f, 0.f);
    #pragma unroll
    for (int i = 0; i < 8; i++) {
        float2 Fv = g_Ff[(b*8 + i)*NF + mk];
        float2 Kv = g_Kf[(i*16 + j)*NF + mk];
        acc.x = fmaf(Fv.x, Kv.x, fmaf(-Fv.y, Kv.y, acc.x));
        acc.y = fmaf(Fv.x, Kv.y, fmaf( Fv.y, Kv.x, acc.y));
    }
    g_Cf[bj*NF + mk] = acc;
}

// ---------------- fused inverse transform: out = Re(Wx * (M.C) * Wy) ----------------
// blocks 0..127   : fr  (from g_Ff, M=1)         -> d_out channels 0..7
// blocks 128..383 : u   (from g_Cf, M=i*MU)      -> g_u
// blocks 384..639 : v   (from g_Cf, M=i*MV)      -> g_v
__global__ void __launch_bounds__(256) k_itrans(float* __restrict__ out) {
    __shared__ float2 Gs[NF];        // [m][k2]   16128 B
    __shared__ float2 Qs[32*128];    // [k2][n1]  32768 B
    int bidx = blockIdx.x;
    const float2* src; float* dst; const float* mul = nullptr;
    if (bidx < 128) {
        src = g_Ff + bidx*NF;
        int b = bidx >> 3, c = bidx & 7;
        dst = out + (size_t)(b*128 + c) * NPIX;
    } else if (bidx < 384) {
        int c2 = bidx - 128; src = g_Cf + c2*NF; dst = g_u + (size_t)c2*NPIX; mul = g_MU;
    } else {
        int c2 = bidx - 384; src = g_Cf + c2*NF; dst = g_v + (size_t)c2*NPIX; mul = g_MV;
    }
    int t = threadIdx.x;
    if (mul) {
        for (int i = t; i < NF; i += 256) {
            float2 cv = src[i]; float m = mul[i];
            Gs[i] = make_float2(-m*cv.y, m*cv.x);   // (i*m) * c
        }
    } else {
        for (int i = t; i < NF; i += 256) Gs[i] = src[i];
    }
    __syncthreads();
    // stage1: Q[k2][n1] = sum_m WxT[m][n1] * G[m][k2]
    {
        int n1 = t & 127, h = t >> 7;   // h selects k2 half [h*16, h*16+16)
        float2 acc[16];
        #pragma unroll
        for (int u = 0; u < 16; u++) acc[u] = make_float2(0.f, 0.f);
        for (int m = 0; m < 63; m++) {
            float2 w = g_WxT[m*128 + n1];           // coalesced
            #pragma unroll
            for (int u = 0; u < 16; u++) {
                float2 g = Gs[m*32 + h*16 + u];     // warp-uniform broadcast
                acc[u].x = fmaf(w.x, g.x, fmaf(-w.y, g.y, acc[u].x));
                acc[u].y = fmaf(w.x, g.y, fmaf( w.y, g.x, acc[u].y));
            }
        }
        #pragma unroll
        for (int u = 0; u < 16; u++) Qs[(h*16 + u)*128 + n1] = acc[u];
    }
    __syncthreads();
    // stage2: out[n1][n2] = sum_k2 (Qr*WyR - Qi*WyI)
    {
        int tx = t & 15, ty = t >> 4;   // 8x8 tile per thread
        float acc2[8][8];
        #pragma unroll
        for (int u = 0; u < 8; u++)
            #pragma unroll
            for (int u2 = 0; u2 < 8; u2++) acc2[u][u2] = 0.f;
        for (int k2 = 0; k2 < 32; k2++) {
            float qr[8], qi[8];
            #pragma unroll
            for (int u = 0; u < 8; u++) {
                float2 q = Qs[k2*128 + ty*8 + u];
                qr[u] = q.x; qi[u] = q.y;
            }
            #pragma unroll
            for (int u2 = 0; u2 < 8; u2++) {
                float2 w = g_WyT[k2*128 + tx*8 + u2];
                #pragma unroll
                for (int u = 0; u < 8; u++)
                    acc2[u][u2] = fmaf(qr[u], w.x, fmaf(-qi[u], w.y, acc2[u][u2]));
            }
        }
        #pragma unroll
        for (int u = 0; u < 8; u++) {
            float4* p = (float4*)(dst + (ty*8 + u)*128 + tx*8);
            p[0] = make_float4(acc2[u][0], acc2[u][1], acc2[u][2], acc2[u][3]);
            p[1] = make_float4(acc2[u][4], acc2[u][5], acc2[u][6], acc2[u][7]);
        }
    }
}

// ---------------- cross products: out[b, 8+p] = u_i v_j - u_j v_i ----------------
__global__ void __launch_bounds__(128) k_cross(float* __restrict__ out) {
    __shared__ float us[16*128], vs[16*128];
    int b = blockIdx.x >> 7, n1 = blockIdx.x & 127;
    int t = threadIdx.x;  // n2
    #pragma unroll
    for (int c = 0; c < 16; c++) {
        us[c*128 + t] = g_u[((size_t)(b*16 + c)*128 + n1)*128 + t];
        vs[c*128 + t] = g_v[((size_t)(b*16 + c)*128 + n1)*128 + t];
    }
    __syncthreads();
    float* obase = out + ((size_t)b*128 + 8) * NPIX + n1*128 + t;
    int i = 0, j = 1;
    for (int p = 0; p < 120; p++) {
        float val = us[i*128 + t] * vs[j*128 + t] - us[j*128 + t] * vs[i*128 + t];
        obase[(size_t)p * NPIX] = val;
        if (++j == 16) { ++i; j = i + 1; }
    }
}

// ---------------- launch ----------------
extern "C" void kernel_launch(void* const* d_in, const int* in_sizes, int n_in,
                              void* d_out, int out_size) {
    const float* f    = (const float*)d_in[0];   // [16,8,64,64]
    const float* kern = (const float*)d_in[1];   // [1,8,16,64,64]
    float* out = (float*)d_out;                  // [16,128,128,128]
    (void)in_sizes; (void)n_in; (void)out_size;

    k_init  <<<1,    256>>>();
    k_sym   <<<2048, 256>>>(kern);
    k_fft64 <<<256,  256>>>(f);
    k_conv  <<<2016, 256>>>();
    k_itrans<<<640,  256>>>(out);
    k_cross <<<2048, 128>>>(out);
}

// round 2
// speedup vs baseline: 1.7941x; 1.7941x over previous
#include <cuda_runtime.h>
#include <math.h>

// Problem constants
#define NBATCH 16
#define NC1 8
#define NC2 16
#define NM 63      /* k1 = m-31, m in [0,63) */
#define NK2 32     /* k2 in [0,32) */
#define NF (NM*NK2)  /* 2016 frequency points */
#define NPIX 16384   /* 128*128 */

// ---------------- device scratch (no allocations allowed) ----------------
__device__ float   g_ksym[128*4096];        // symmetrized kernel [8*16][64][64]
__device__ float2  g_Kf[128*NF];            // K spectrum   [i*16+j][m][k2]
__device__ float2  g_Ff[128*NF];            // F spectrum   [b*8+i][m][k2]
__device__ float2  g_Cf[256*NF];            // conv spectrum [b*16+j][m][k2]
__device__ float   g_u[256*NPIX];           // u fields [b*16+j][128][128]
__device__ float   g_v[256*NPIX];
// twiddle tables
__device__ float2  g_Ey[64*32];             // e^{-2pi i k2 y/64}   [y][k2]
__device__ float2  g_Ex[64*64];             // e^{-2pi i (m-31) x/64} [m][x]
__device__ float2  g_WxT[63*128];           // e^{+2pi i (m-31) n1/128} [m][n1]
__device__ float2  g_WyT[32*128];           // scaled e^{+2pi i k2 n2/128} [k2][n2]
__device__ float   g_MU[NF];                // imag multiplier for u:  ky/den
__device__ float   g_MV[NF];                // imag multiplier for v: -kx/den

// ---------------- table init ----------------
__global__ void k_init() {
    int t = threadIdx.x;
    for (int idx = t; idx < 64*32; idx += 256) {
        int y = idx >> 5, k2 = idx & 31;
        float s, c; sincospif(-2.0f * (float)(k2*y) / 64.0f, &s, &c);
        g_Ey[idx] = make_float2(c, s);
    }
    for (int idx = t; idx < 64*64; idx += 256) {
        int m = idx >> 6, x = idx & 63; int k1 = m - 31;
        float s, c; sincospif(-2.0f * (float)(k1*x) / 64.0f, &s, &c);
        g_Ex[idx] = make_float2(c, s);
    }
    for (int idx = t; idx < 63*128; idx += 256) {
        int m = idx >> 7, n1 = idx & 127; int k1 = m - 31;
        float s, c; sincospif(2.0f * (float)(k1*n1) / 128.0f, &s, &c);
        g_WxT[idx] = make_float2(c, s);
    }
    for (int idx = t; idx < 32*128; idx += 256) {
        int k2 = idx >> 7, n2 = idx & 127;
        float s, c; sincospif(2.0f * (float)(k2*n2) / 128.0f, &s, &c);
        float sc = ((k2 == 0) ? 1.0f : 2.0f) * (2.0f / 16384.0f);
        g_WyT[idx] = make_float2(c * sc, s * sc);
    }
    for (int idx = t; idx < NF; idx += 256) {
        int m = idx >> 5, k2 = idx & 31; int k1 = m - 31;
        float den = (float)(k1*k1 + k2*k2);
        if (den == 0.0f) den = 1.0f;
        g_MU[idx] =  (float)k2 / den;
        g_MV[idx] = -(float)k1 / den;
    }
}

// ---------------- D4 kernel symmetrization ----------------
__global__ void k_sym(const float* __restrict__ kin) {
    int idx = blockIdx.x * 256 + threadIdx.x;     // 128*4096 total
    int ch = idx >> 12;
    int rem = idx & 4095;
    int a = rem >> 6, b = rem & 63;
    int na = (64 - a) & 63, nb = (64 - b) & 63;
    const float* s = kin + ch * 4096;
    float v = s[a*64 + b]   + s[nb*64 + a]  + s[na*64 + nb] + s[b*64 + na]
            + s[b*64 + a]   + s[a*64 + nb]  + s[nb*64 + na] + s[na*64 + b];
    g_ksym[idx] = v * 0.125f;
}

// ---------------- forward DFT to the 63x32 grid ----------------
__global__ void __launch_bounds__(256) k_fft64(const float* __restrict__ f) {
    __shared__ float  ss[4096];      // [x][y]
    __shared__ float2 sA[2048];      // [x][k2]
    int ch = blockIdx.x;
    const float* src = (ch < 128) ? (g_ksym + ch*4096) : (f + (ch-128)*4096);
    int t = threadIdx.x;
    for (int i = t; i < 4096; i += 256) ss[i] = src[i];
    __syncthreads();
    int k2 = t & 31, grp = t >> 5;
    {
        float2 acc[8];
        #pragma unroll
        for (int r = 0; r < 8; r++) acc[r] = make_float2(0.f, 0.f);
        for (int y = 0; y < 64; y++) {
            float2 e = g_Ey[y*32 + k2];
            #pragma unroll
            for (int r = 0; r < 8; r++) {
                float sv = ss[(grp*8 + r)*64 + y];
                acc[r].x = fmaf(sv, e.x, acc[r].x);
                acc[r].y = fmaf(sv, e.y, acc[r].y);
            }
        }
        #pragma unroll
        for (int r = 0; r < 8; r++) sA[(grp*8 + r)*32 + k2] = acc[r];
    }
    __syncthreads();
    {
        float2 acc[8];
        #pragma unroll
        for (int r = 0; r < 8; r++) acc[r] = make_float2(0.f, 0.f);
        for (int x = 0; x < 64; x++) {
            #pragma unroll
            for (int r = 0; r < 8; r++) {
                int m = grp*8 + r;
                float2 e = g_Ex[m*64 + x];
                float2 a = sA[x*32 + k2];
                acc[r].x = fmaf(e.x, a.x, fmaf(-e.y, a.y, acc[r].x));
                acc[r].y = fmaf(e.x, a.y, fmaf( e.y, a.x, acc[r].y));
            }
        }
        float2* dstF = (ch < 128) ? (g_Kf + ch*NF) : (g_Ff + (ch-128)*NF);
        #pragma unroll
        for (int r = 0; r < 8; r++) {
            int m = grp*8 + r;
            if (m < 63) dstF[m*32 + k2] = acc[r];
        }
    }
}

// ---------------- channel contraction ----------------
__global__ void k_conv() {
    int idx = blockIdx.x * 256 + threadIdx.x;
    int mk = idx % NF;
    int bj = idx / NF;
    int b = bj >> 4, j = bj & 15;
    float2 acc = make_float2(0.f, 0.f);
    #pragma unroll
    for (int i = 0; i < 8; i++) {
        float2 Fv = g_Ff[(b*8 + i)*NF + mk];
        float2 Kv = g_Kf[(i*16 + j)*NF + mk];
        acc.x = fmaf(Fv.x, Kv.x, fmaf(-Fv.y, Kv.y, acc.x));
        acc.y = fmaf(Fv.x, Kv.y, fmaf( Fv.y, Kv.x, acc.y));
    }
    g_Cf[bj*NF + mk] = acc;
}

// ---------------- fused inverse transform with +/-k symmetry ----------------
// out(n1,n2) = Re( Wx * G * Wy ), computed with conjugate-pair folding:
//  stage1: S=G(k1)+G(-k1), D=G(k1)-G(-k1); P=sum c*Sr, R=sum s*Di, T=sum c*Si, U=sum s*Dr
//          -> Q(n1)=(Zr+P-R, Zi+T+U), Q(128-n1)=(Zr+P+R, Zi+T-U)
//  stage2: E=sum wc*Qr, O=sum ws*Qi -> out(n2)=E-O, out(128-n2)=E+O
#define SM_Z    16384
#define SM_Q    16640
#define SM_TOT  (16640 + 32768)

__global__ void __launch_bounds__(256) k_itrans(float* __restrict__ out) {
    extern __shared__ char sm[];
    float2* Gs = (float2*)sm;                 // 2016 float2 (reused as SD)
    float4* SD = (float4*)sm;                 // SD[(k1-1)*32+k2] = (Sr,Si,Dr,Di)
    float2* Zs = (float2*)(sm + SM_Z);        // 32
    float2* Qs = (float2*)(sm + SM_Q);        // [k2][n1] 32x128

    int bidx = blockIdx.x;
    const float2* src; float* dst; const float* mul = nullptr;
    if (bidx < 128) {
        src = g_Ff + bidx*NF;
        int b = bidx >> 3, c = bidx & 7;
        dst = out + (size_t)(b*128 + c) * NPIX;
    } else if (bidx < 384) {
        int c2 = bidx - 128; src = g_Cf + c2*NF; dst = g_u + (size_t)c2*NPIX; mul = g_MU;
    } else {
        int c2 = bidx - 384; src = g_Cf + c2*NF; dst = g_v + (size_t)c2*NPIX; mul = g_MV;
    }
    int t = threadIdx.x;

    // phase 0: load G (with multiplier folded: (i*m)*c for u/v)
    if (mul) {
        for (int i = t; i < NF; i += 256) {
            float2 cv = src[i]; float m = mul[i];
            Gs[i] = make_float2(-m*cv.y, m*cv.x);
        }
    } else {
        for (int i = t; i < NF; i += 256) Gs[i] = src[i];
    }
    __syncthreads();

    // phase 1: build S/D pairs in registers, then overwrite smem in place
    float4 rv[4];
    #pragma unroll
    for (int r = 0; r < 4; r++) {
        int e = t + 256*r;
        if (e < 992) {
            int k1 = (e >> 5) + 1, k2 = e & 31;
            float2 gp = Gs[(31 + k1)*32 + k2];
            float2 gm = Gs[(31 - k1)*32 + k2];
            rv[r] = make_float4(gp.x + gm.x, gp.y + gm.y, gp.x - gm.x, gp.y - gm.y);
        }
    }
    float2 zv;
    if (t < 32) zv = Gs[31*32 + t];
    __syncthreads();
    #pragma unroll
    for (int r = 0; r < 4; r++) {
        int e = t + 256*r;
        if (e < 992) SD[e] = rv[r];
    }
    if (t < 32) Zs[t] = zv;
    __syncthreads();

    // phase 2a: n1 = 64 column of Q (sin == 0 there)
    if (t < 32) {
        float2 z = Zs[t];
        float pr = z.x, pi = z.y;
        for (int k1 = 1; k1 < 32; k1++) {
            float4 sd = SD[(k1-1)*32 + t];
            float sgn = (k1 & 1) ? -1.0f : 1.0f;
            pr = fmaf(sgn, sd.x, pr);
            pi = fmaf(sgn, sd.y, pi);
        }
        Qs[t*128 + 64] = make_float2(pr, pi);
    }

    // phase 2b: stage1 main — each thread: one n1h (0..63) x 8 k2
    {
        int n1 = t & 63, kg = t >> 6, k2b = kg*8;
        float P[8], R[8], T[8], U[8];
        #pragma unroll
        for (int u = 0; u < 8; u++) { P[u]=0.f; R[u]=0.f; T[u]=0.f; U[u]=0.f; }
        for (int k1 = 1; k1 < 32; k1++) {
            float2 w = g_WxT[(31 + k1)*128 + n1];
            #pragma unroll
            for (int u = 0; u < 8; u++) {
                float4 sd = SD[(k1-1)*32 + k2b + u];
                P[u] = fmaf(w.x, sd.x, P[u]);
                T[u] = fmaf(w.x, sd.y, T[u]);
                U[u] = fmaf(w.y, sd.z, U[u]);
                R[u] = fmaf(w.y, sd.w, R[u]);
            }
        }
        int n1p = (128 - n1) & 127;
        #pragma unroll
        for (int u = 0; u < 8; u++) {
            float2 z = Zs[k2b + u];
            Qs[(k2b + u)*128 + n1]  = make_float2(z.x + P[u] - R[u], z.y + T[u] + U[u]);
            Qs[(k2b + u)*128 + n1p] = make_float2(z.x + P[u] + R[u], z.y + T[u] - U[u]);
        }
    }
    __syncthreads();

    // phase 3a: n2 = 64 column of output (sin == 0 there)
    if (t < 128) {
        float acc = 0.f;
        for (int k2 = 0; k2 < 32; k2++)
            acc = fmaf(g_WyT[k2*128 + 64].x, Qs[k2*128 + t].x, acc);
        dst[t*128 + 64] = acc;
    }

    // phase 3b: stage2 main — thread tile: 8 n1 x 4 n2h (each pair -> 2 outputs)
    {
        int tx = t & 15, ty = t >> 4;      // n2 = tx*4+j (0..63), n1 = ty*8+u
        float E[8][4], O[8][4];
        #pragma unroll
        for (int u = 0; u < 8; u++)
            #pragma unroll
            for (int j = 0; j < 4; j++) { E[u][j] = 0.f; O[u][j] = 0.f; }
        for (int k2 = 0; k2 < 32; k2++) {
            float2 w[4];
            #pragma unroll
            for (int j = 0; j < 4; j++) w[j] = g_WyT[k2*128 + tx*4 + j];
            float qr[8], qi[8];
            #pragma unroll
            for (int u = 0; u < 8; u++) {
                float2 q = Qs[k2*128 + ty*8 + u];
                qr[u] = q.x; qi[u] = q.y;
            }
            #pragma unroll
            for (int u = 0; u < 8; u++)
                #pragma unroll
                for (int j = 0; j < 4; j++) {
                    E[u][j] = fmaf(qr[u], w[j].x, E[u][j]);
                    O[u][j] = fmaf(qi[u], w[j].y, O[u][j]);
                }
        }
        #pragma unroll
        for (int u = 0; u < 8; u++) {
            float* row = dst + (ty*8 + u)*128;
            *(float4*)(row + tx*4) = make_float4(E[u][0]-O[u][0], E[u][1]-O[u][1],
                                                 E[u][2]-O[u][2], E[u][3]-O[u][3]);
            #pragma unroll
            for (int j = 0; j < 4; j++)
                row[(128 - (tx*4 + j)) & 127] = E[u][j] + O[u][j];
        }
    }
}

// ---------------- cross products ----------------
__global__ void __launch_bounds__(128) k_cross(float* __restrict__ out) {
    __shared__ float us[16*128], vs[16*128];
    int b = blockIdx.x >> 7, n1 = blockIdx.x & 127;
    int t = threadIdx.x;
    #pragma unroll
    for (int c = 0; c < 16; c++) {
        us[c*128 + t] = g_u[((size_t)(b*16 + c)*128 + n1)*128 + t];
        vs[c*128 + t] = g_v[((size_t)(b*16 + c)*128 + n1)*128 + t];
    }
    __syncthreads();
    float* obase = out + ((size_t)b*128 + 8) * NPIX + n1*128 + t;
    int i = 0, j = 1;
    for (int p = 0; p < 120; p++) {
        float val = us[i*128 + t] * vs[j*128 + t] - us[j*128 + t] * vs[i*128 + t];
        obase[(size_t)p * NPIX] = val;
        if (++j == 16) { ++i; j = i + 1; }
    }
}

// ---------------- launch ----------------
extern "C" void kernel_launch(void* const* d_in, const int* in_sizes, int n_in,
                              void* d_out, int out_size) {
    const float* f    = (const float*)d_in[0];   // [16,8,64,64]
    const float* kern = (const float*)d_in[1];   // [1,8,16,64,64]
    float* out = (float*)d_out;                  // [16,128,128,128]
    (void)in_sizes; (void)n_in; (void)out_size;

    cudaFuncSetAttribute(k_itrans, cudaFuncAttributeMaxDynamicSharedMemorySize, SM_TOT);

    k_init  <<<1,    256>>>();
    k_sym   <<<2048, 256>>>(kern);
    k_fft64 <<<256,  256>>>(f);
    k_conv  <<<2016, 256>>>();
    k_itrans<<<640,  256, SM_TOT>>>(out);
    k_cross <<<2048, 128>>>(out);
}